// round 8
// baseline (speedup 1.0000x reference)
#include <cuda_runtime.h>
#include <cuda_bf16.h>

// loss[s] = -(1/496)*[ sum_i x_i*(31-i) - sum_{i<j} ln(e_i+e_j) + 0.0005*sum_i x_i^2*(31-2i) ]
// via log_sigmoid(x_i - x_j) == x_i - ln(e^{x_i} + e^{x_j}).
//
// sum_{pairs} ln = ln(prod): per lane ONE 16-term fp32 product of
// (e_i+e_j)/2 terms (prescale 2^-1 keeps the exponent in range; correction
// folds into a per-lane constant), one lg2 at the end.
//
// 8 segments per warp as 4 packed f32x2 chains: the pair core is
// 4 LDS.64 + 4 add2 + 4 mul2 per offset, amortized over 8 segments.

static constexpr float INV_PAIRS = 1.0f / 496.0f;
static constexpr float LN2  = 0.69314718055994530942f;
static constexpr float L2E  = 1.44269504088896340736f;
static constexpr int   WPB  = 4;                 // warps per block (128 thr)
static constexpr int   SEG_PER_WARP = 8;
static constexpr int   SEG_PER_BLOCK = WPB * SEG_PER_WARP;  // 32

typedef unsigned long long u64;
typedef unsigned int u32;

__device__ __forceinline__ u64 pk(float lo, float hi) {
    u64 r; asm("mov.b64 %0,{%1,%2};" : "=l"(r) : "f"(lo), "f"(hi)); return r;
}
__device__ __forceinline__ void upk(u64 v, float& lo, float& hi) {
    asm("mov.b64 {%0,%1},%2;" : "=f"(lo), "=f"(hi) : "l"(v));
}
__device__ __forceinline__ u64 add2(u64 a, u64 b) {
    u64 r; asm("add.rn.f32x2 %0,%1,%2;" : "=l"(r) : "l"(a), "l"(b)); return r;
}
__device__ __forceinline__ u64 mul2(u64 a, u64 b) {
    u64 r; asm("mul.rn.f32x2 %0,%1,%2;" : "=l"(r) : "l"(a), "l"(b)); return r;
}
__device__ __forceinline__ float ex2(float x) {
    float r; asm("ex2.approx.f32 %0,%1;" : "=f"(r) : "f"(x)); return r;
}
__device__ __forceinline__ float lg2(float x) {
    float r; asm("lg2.approx.f32 %0,%1;" : "=f"(r) : "f"(x)); return r;
}
// log2 of a renorm-free product: (E-127) + lg2(mantissa in [1,2)).
__device__ __forceinline__ float log2p(float p) {
    u32 b = __float_as_uint(p);
    float m = __uint_as_float((b & 0x007FFFFFu) | 0x3F800000u);
    return (float)((int)(b >> 23) - 127) + lg2(m);
}

__global__ __launch_bounds__(WPB * 32)
void rmloss_kernel(const float* __restrict__ logits,
                   float4* __restrict__ out,
                   int n_seg)
{
    __shared__ u64 ring[4][WPB][64];   // 4 packed chains, duplicated rings

    const int w    = threadIdx.x >> 5;
    const int lane = threadIdx.x & 31;
    const int gw   = blockIdx.x * WPB + w;          // warp index (0..4095)
    const int s0   = gw * SEG_PER_WARP;
    if (s0 >= n_seg) return;

    const float* base = logits + (size_t)s0 * 32 + lane;
    const float x0 = base[0],   x1 = base[32],  x2 = base[64],  x3 = base[96];
    const float x4 = base[128], x5 = base[160], x6 = base[192], x7 = base[224];

    // e = exp(x)/2 = exp2(x*log2e - 1): prescale keeps the 16-term product
    // exponent-safe; correction folded into KPS below.
    const float e0 = ex2(fmaf(x0, L2E, -1.0f));
    const float e1 = ex2(fmaf(x1, L2E, -1.0f));
    const float e2 = ex2(fmaf(x2, L2E, -1.0f));
    const float e3 = ex2(fmaf(x3, L2E, -1.0f));
    const float e4 = ex2(fmaf(x4, L2E, -1.0f));
    const float e5 = ex2(fmaf(x5, L2E, -1.0f));
    const float e6 = ex2(fmaf(x6, L2E, -1.0f));
    const float e7 = ex2(fmaf(x7, L2E, -1.0f));

    const u64 E0 = pk(e0, e1), E1 = pk(e2, e3);
    const u64 E2 = pk(e4, e5), E3 = pk(e6, e7);

    // Fill duplicated rings (pair reads become LDS.64 [base + imm]).
    ring[0][w][lane] = E0;  ring[0][w][lane + 32] = E0;
    ring[1][w][lane] = E1;  ring[1][w][lane + 32] = E1;
    ring[2][w][lane] = E2;  ring[2][w][lane + 32] = E2;
    ring[3][w][lane] = E3;  ring[3][w][lane + 32] = E3;
    __syncwarp();

    // Single 16-term product per chain. Offsets 1..15: each unordered pair
    // exactly once; offset 16 only lanes 0..15 (upper half multiplies by 1).
    u64 p0 = add2(E0, ring[0][w][lane + 1]);
    u64 p1 = add2(E1, ring[1][w][lane + 1]);
    u64 p2 = add2(E2, ring[2][w][lane + 1]);
    u64 p3 = add2(E3, ring[3][w][lane + 1]);
    #pragma unroll
    for (int o = 2; o <= 15; ++o) {
        p0 = mul2(p0, add2(E0, ring[0][w][lane + o]));
        p1 = mul2(p1, add2(E1, ring[1][w][lane + o]));
        p2 = mul2(p2, add2(E2, ring[2][w][lane + o]));
        p3 = mul2(p3, add2(E3, ring[3][w][lane + o]));
    }
    {
        const u64 ONE = 0x3F8000003F800000ull;   // (1.0f, 1.0f)
        const bool lo16 = (lane < 16);
        p0 = mul2(p0, lo16 ? add2(E0, ring[0][w][lane + 16]) : ONE);
        p1 = mul2(p1, lo16 ? add2(E1, ring[1][w][lane + 16]) : ONE);
        p2 = mul2(p2, lo16 ? add2(E2, ring[2][w][lane + 16]) : ONE);
        p3 = mul2(p3, lo16 ? add2(E3, ring[3][w][lane + 16]) : ONE);
    }

    // Per-lane constants (all scale factors folded in).
    const float CL  = (float)(31 - lane)     * (-INV_PAIRS);
    const float CQ  = (float)(31 - 2 * lane) * (-0.0005f * INV_PAIRS);
    const float CLN = LN2 * INV_PAIRS;
    // prescale correction: n terms of 2^-1 -> add n to log2(prod)
    const float KPS = CLN * ((lane < 16) ? 16.0f : 15.0f);

    float f0, f1, f2, f3, f4, f5, f6, f7;
    upk(p0, f0, f1); upk(p1, f2, f3); upk(p2, f4, f5); upk(p3, f6, f7);

    float t0 = fmaf(log2p(f0), CLN, KPS);
    float t1 = fmaf(log2p(f1), CLN, KPS);
    float t2 = fmaf(log2p(f2), CLN, KPS);
    float t3 = fmaf(log2p(f3), CLN, KPS);
    float t4 = fmaf(log2p(f4), CLN, KPS);
    float t5 = fmaf(log2p(f5), CLN, KPS);
    float t6 = fmaf(log2p(f6), CLN, KPS);
    float t7 = fmaf(log2p(f7), CLN, KPS);

    t0 = fmaf(x0, CL, t0);  t0 = fmaf(x0 * x0, CQ, t0);
    t1 = fmaf(x1, CL, t1);  t1 = fmaf(x1 * x1, CQ, t1);
    t2 = fmaf(x2, CL, t2);  t2 = fmaf(x2 * x2, CQ, t2);
    t3 = fmaf(x3, CL, t3);  t3 = fmaf(x3 * x3, CQ, t3);
    t4 = fmaf(x4, CL, t4);  t4 = fmaf(x4 * x4, CQ, t4);
    t5 = fmaf(x5, CL, t5);  t5 = fmaf(x5 * x5, CQ, t5);
    t6 = fmaf(x6, CL, t6);  t6 = fmaf(x6 * x6, CQ, t6);
    t7 = fmaf(x7, CL, t7);  t7 = fmaf(x7 * x7, CQ, t7);

    // Butterfly on packed u64 (2 SHFL + 1 add2 per chain-step).
    u64 v0 = pk(t0, t1), v1 = pk(t2, t3), v2 = pk(t4, t5), v3 = pk(t6, t7);
    #pragma unroll
    for (int m = 16; m >= 1; m >>= 1) {
        v0 = add2(v0, __shfl_xor_sync(0xFFFFFFFFu, v0, m));
        v1 = add2(v1, __shfl_xor_sync(0xFFFFFFFFu, v1, m));
        v2 = add2(v2, __shfl_xor_sync(0xFFFFFFFFu, v2, m));
        v3 = add2(v3, __shfl_xor_sync(0xFFFFFFFFu, v3, m));
    }

    if (lane == 0) {
        float a0, a1, a2, a3, a4, a5, a6, a7;
        upk(v0, a0, a1); upk(v1, a2, a3); upk(v2, a4, a5); upk(v3, a6, a7);
        out[2 * gw]     = make_float4(a0, a1, a2, a3);
        out[2 * gw + 1] = make_float4(a4, a5, a6, a7);
    }
}

extern "C" void kernel_launch(void* const* d_in, const int* in_sizes, int n_in,
                              void* d_out, int out_size)
{
    const float* logits = (const float*)d_in[0];
    float4* out = (float4*)d_out;
    const int n_seg = out_size;                  // 32768

    const int threads = WPB * 32;                // 128
    const int blocks = (n_seg + SEG_PER_BLOCK - 1) / SEG_PER_BLOCK;   // 1024
    rmloss_kernel<<<blocks, threads>>>(logits, out, n_seg);
}